// round 10
// baseline (speedup 1.0000x reference)
#include <cuda_runtime.h>

// Windowed local attention, k=7, H=W=256, C=32, fp32.
// Thread = (vertical pixel pair, union-row QUARTER): 4 threads per pixel
// pair, each owning 2 of the 8 union window rows. 28 score accumulators.
// Tile 32x4, 256 threads, halo 38x10 (stride 44), smem 55KB, 3 blocks/SM.
// Lane = q*8+pxl -> quarter smem offsets {0,24,16,8} mod 32: conflict-free.

#define H_IMG 256
#define W_IMG 256
#define C 32
#define K 7
#define PAD 3
#define TX 32
#define TY 4
#define HW 38               // used cols
#define HWS 44              // padded row stride (2*44 % 32 == 24)
#define HH 10               // TY + 6
#define CHST (HH * HWS)     // 440 floats per channel
#define NTHREADS 256
#define SMEM_BYTES (C * CHST * 4)   // 56320

// Stage one tensor's halo: [c][row*HWS + col], zero-padded OOB.
__device__ __forceinline__ void stage_halo(float* __restrict__ buf,
                                           const float* __restrict__ src,
                                           int bx, int by, int tid) {
    for (int p = tid; p < HW * HH; p += NTHREADS) {
        int hp = p / HW;
        int wp = p - hp * HW;
        int gw = bx * TX - PAD + wp;
        int gh = by * TY - PAD + hp;
        bool ok = (gw >= 0) && (gw < W_IMG) && (gh >= 0) && (gh < H_IMG);
        int sa = hp * HWS + wp;
        int ga = ((gh << 8) + gw) * C;
        #pragma unroll
        for (int g = 0; g < 8; g++) {
            float4 r = make_float4(0.f, 0.f, 0.f, 0.f);
            if (ok) r = *reinterpret_cast<const float4*>(src + ga + (g << 2));
            float* d = buf + (g << 2) * CHST + sa;
            d[0 * CHST] = r.x;
            d[1 * CHST] = r.y;
            d[2 * CHST] = r.z;
            d[3 * CHST] = r.w;
        }
    }
}

__global__ __launch_bounds__(NTHREADS, 3)
void local_attn_kernel(const float* __restrict__ main_in,
                       const float* __restrict__ ref_in,
                       const float* __restrict__ val_in,
                       float* __restrict__ out) {
    extern __shared__ float smem[];

    const int tid  = threadIdx.x;
    const int bx   = blockIdx.x, by = blockIdx.y;
    const int warp = tid >> 5;
    const int lane = tid & 31;
    const int q    = lane >> 3;                    // row quarter 0..3
    const int pxl  = lane & 7;
    const int px   = ((warp & 3) << 3) + pxl;      // tile col 0..31
    const int pr   = warp >> 2;                    // pixel-pair row 0..1

    // This quarter's first union row within the halo:
    const int sbase = (2 * pr + 2 * q) * HWS + px;

    const int gy0   = by * TY + 2 * pr;
    const int gpix0 = ((gy0 << 8) + bx * TX + px) * C;   // pixel0 (row 2pr)
    const int gpix1 = gpix0 + W_IMG * C;                 // pixel1

    // Row validity: pixel0 uses union rows 0..6, pixel1 uses 1..7.
    const bool pv0 = (2 * q + 0) <= 6, pv1 = (2 * q + 1) <= 6;  // pv1 false iff q==3
    const bool sv0 = (2 * q + 0) >= 1, sv1 = true;              // sv0 false iff q==0

    // ---- Stage ref halo ----
    stage_halo(smem, ref_in, bx, by, tid);
    __syncthreads();

    // ---- Pass 1: partial scores over this quarter's 2 rows x 7 cols ----
    float prim[14], seco[14];
    #pragma unroll
    for (int i = 0; i < 14; i++) { prim[i] = 0.f; seco[i] = 0.f; }

    #pragma unroll
    for (int cc = 0; cc < 4; cc++) {               // 8-channel chunks
        float qp[8], qs[8];
        #pragma unroll
        for (int i = 0; i < 2; i++) {
            float4 a = *reinterpret_cast<const float4*>(main_in + gpix0 + cc * 8 + 4 * i);
            float4 b = *reinterpret_cast<const float4*>(main_in + gpix1 + cc * 8 + 4 * i);
            qp[4 * i + 0] = a.x; qp[4 * i + 1] = a.y; qp[4 * i + 2] = a.z; qp[4 * i + 3] = a.w;
            qs[4 * i + 0] = b.x; qs[4 * i + 1] = b.y; qs[4 * i + 2] = b.z; qs[4 * i + 3] = b.w;
        }
        #pragma unroll
        for (int c = 0; c < 8; c++) {
            const float* base = smem + (cc * 8 + c) * CHST + sbase;
            #pragma unroll
            for (int lr = 0; lr < 2; lr++) {
                #pragma unroll
                for (int dw = 0; dw < K; dw++) {
                    float v = base[lr * HWS + dw];
                    prim[lr * 7 + dw] = fmaf(v, qp[c], prim[lr * 7 + dw]);
                    seco[lr * 7 + dw] = fmaf(v, qs[c], seco[lr * 7 + dw]);
                }
            }
        }
    }

    // ---- Distributed softmax across the 4 quarter-lanes (xor 8, xor 16) ----
    // (OOB halo positions carry score 0 and are included, matching reference.)
    float lmP = -1e30f, lmS = -1e30f;
    #pragma unroll
    for (int dw = 0; dw < K; dw++) {
        lmP = fmaxf(lmP, pv0 ? prim[dw] : -1e30f);
        lmP = fmaxf(lmP, pv1 ? prim[7 + dw] : -1e30f);
        lmS = fmaxf(lmS, sv0 ? seco[dw] : -1e30f);
        lmS = fmaxf(lmS, sv1 ? seco[7 + dw] : -1e30f);
    }
    lmP = fmaxf(lmP, __shfl_xor_sync(0xffffffffu, lmP, 8));
    lmP = fmaxf(lmP, __shfl_xor_sync(0xffffffffu, lmP, 16));
    lmS = fmaxf(lmS, __shfl_xor_sync(0xffffffffu, lmS, 8));
    lmS = fmaxf(lmS, __shfl_xor_sync(0xffffffffu, lmS, 16));

    float lsP = 0.f, lsS = 0.f;
    #pragma unroll
    for (int dw = 0; dw < K; dw++) {
        prim[dw]     = pv0 ? __expf(prim[dw] - lmP) : 0.f;
        prim[7 + dw] = pv1 ? __expf(prim[7 + dw] - lmP) : 0.f;
        seco[dw]     = sv0 ? __expf(seco[dw] - lmS) : 0.f;
        seco[7 + dw] = sv1 ? __expf(seco[7 + dw] - lmS) : 0.f;
        lsP += prim[dw] + prim[7 + dw];
        lsS += seco[dw] + seco[7 + dw];
    }
    lsP += __shfl_xor_sync(0xffffffffu, lsP, 8);
    lsP += __shfl_xor_sync(0xffffffffu, lsP, 16);
    lsS += __shfl_xor_sync(0xffffffffu, lsS, 8);
    lsS += __shfl_xor_sync(0xffffffffu, lsS, 16);
    float ivP = 1.f / lsP, ivS = 1.f / lsS;
    #pragma unroll
    for (int i = 0; i < 14; i++) { prim[i] *= ivP; seco[i] *= ivS; }

    // ---- Stage val halo (reuse buffer) ----
    __syncthreads();
    stage_halo(smem, val_in, bx, by, tid);
    __syncthreads();

    // ---- Pass 2: partial outputs; xor-combine; split stores ----
    #pragma unroll
    for (int g = 0; g < 8; g++) {
        float oP[4] = {0.f, 0.f, 0.f, 0.f};
        float oS[4] = {0.f, 0.f, 0.f, 0.f};
        #pragma unroll
        for (int c = 0; c < 4; c++) {
            const float* base = smem + ((g << 2) + c) * CHST + sbase;
            #pragma unroll
            for (int lr = 0; lr < 2; lr++) {
                #pragma unroll
                for (int dw = 0; dw < K; dw++) {
                    float v = base[lr * HWS + dw];
                    oP[c] = fmaf(v, prim[lr * 7 + dw], oP[c]);
                    oS[c] = fmaf(v, seco[lr * 7 + dw], oS[c]);
                }
            }
        }
        #pragma unroll
        for (int c = 0; c < 4; c++) {
            oP[c] += __shfl_xor_sync(0xffffffffu, oP[c], 8);
            oP[c] += __shfl_xor_sync(0xffffffffu, oP[c], 16);
            oS[c] += __shfl_xor_sync(0xffffffffu, oS[c], 8);
            oS[c] += __shfl_xor_sync(0xffffffffu, oS[c], 16);
        }
        // quarter q: stores pixel (q>>1), channel-group half (q&1)
        if ((g >> 2) == (q & 1)) {
            int base_g = (q >> 1) ? gpix1 : gpix0;
            const float* src4 = (q >> 1) ? oS : oP;
            *reinterpret_cast<float4*>(out + base_g + (g << 2)) =
                make_float4(src4[0], src4[1], src4[2], src4[3]);
        }
    }
}

extern "C" void kernel_launch(void* const* d_in, const int* in_sizes, int n_in,
                              void* d_out, int out_size) {
    const float* main_in = (const float*)d_in[0];
    const float* ref_in  = (const float*)d_in[1];
    const float* val_in  = (const float*)d_in[2];
    float* out = (float*)d_out;

    cudaFuncSetAttribute(local_attn_kernel,
                         cudaFuncAttributeMaxDynamicSharedMemorySize, SMEM_BYTES);

    dim3 grid(W_IMG / TX, H_IMG / TY);
    local_attn_kernel<<<grid, NTHREADS, SMEM_BYTES>>>(main_in, ref_in, val_in, out);
}

// round 11
// speedup vs baseline: 1.0887x; 1.0887x over previous
#include <cuda_runtime.h>

// Windowed local attention, k=7, H=W=256, C=32, fp32.
// Thread = (vertical pixel-pair, window-row half); 56 accumulators.
// Tile 32x4, 128 threads, halo 38x10 (row stride 44 -> half-offset 176 ==
// 16 mod 32, conflict-free LDS). Smem 56.3KB -> 4 blocks/SM, 16 warps/SM
// in 4 independent CTAs so staging/sync phases overlap across blocks.

#define H_IMG 256
#define W_IMG 256
#define C 32
#define K 7
#define PAD 3
#define TX 32
#define TY 4
#define HW 38               // used cols
#define HWS 44              // padded row stride (4*44 % 32 == 16)
#define HH 10               // TY + 6
#define CHST (HH * HWS)     // 440 floats per channel
#define NTHREADS 128
#define SMEM_BYTES (C * CHST * 4)   // 56320

// Stage one tensor's halo: [c][row*HWS + col], zero-padded OOB.
__device__ __forceinline__ void stage_halo(float* __restrict__ buf,
                                           const float* __restrict__ src,
                                           int bx, int by, int tid) {
    for (int p = tid; p < HW * HH; p += NTHREADS) {
        int hp = p / HW;
        int wp = p - hp * HW;
        int gw = bx * TX - PAD + wp;
        int gh = by * TY - PAD + hp;
        bool ok = (gw >= 0) && (gw < W_IMG) && (gh >= 0) && (gh < H_IMG);
        int sa = hp * HWS + wp;
        int ga = ((gh << 8) + gw) * C;
        #pragma unroll
        for (int g = 0; g < 8; g++) {
            float4 r = make_float4(0.f, 0.f, 0.f, 0.f);
            if (ok) r = *reinterpret_cast<const float4*>(src + ga + (g << 2));
            float* d = buf + (g << 2) * CHST + sa;
            d[0 * CHST] = r.x;
            d[1 * CHST] = r.y;
            d[2 * CHST] = r.z;
            d[3 * CHST] = r.w;
        }
    }
}

__global__ __launch_bounds__(NTHREADS, 4)
void local_attn_kernel(const float* __restrict__ main_in,
                       const float* __restrict__ ref_in,
                       const float* __restrict__ val_in,
                       float* __restrict__ out) {
    extern __shared__ float smem[];

    const int tid  = threadIdx.x;
    const int bx   = blockIdx.x, by = blockIdx.y;
    const int warp = tid >> 5;            // 0..3
    const int lane = tid & 31;
    const int half = lane >> 4;           // 0: union rows 0-3, 1: rows 4-7
    const int pr   = warp >> 1;           // pixel-pair row 0..1
    const int px   = ((warp & 1) << 4) + (lane & 15);   // tile col 0..31

    const int sbase = (2 * pr + 4 * half) * HWS + px;

    const int gy0   = by * TY + 2 * pr;
    const int gpix0 = ((gy0 << 8) + bx * TX + px) * C;   // pixel0 (row 2pr)
    const int gpix1 = gpix0 + W_IMG * C;                 // pixel1 (row 2pr+1)
    const int gprim = half ? gpix1 : gpix0;              // primary pixel
    const int gseco = half ? gpix0 : gpix1;              // secondary pixel

    // ---- Stage ref halo ----
    stage_halo(smem, ref_in, bx, by, tid);
    __syncthreads();

    // ---- Pass 1: prim/seco partial scores over 4 local rows x 7 cols ----
    // prim[r*7+dw]: primary pixel's contribution at local row r.
    // seco[r*7+dw]: secondary pixel's (half A: valid r>=1, half B: r<=2).
    float prim[28], seco[28];
    #pragma unroll
    for (int i = 0; i < 28; i++) { prim[i] = 0.f; seco[i] = 0.f; }

    #pragma unroll
    for (int cc = 0; cc < 4; cc++) {                 // 8-channel chunks
        float qp[8], qs[8];
        #pragma unroll
        for (int i = 0; i < 2; i++) {
            float4 a = *reinterpret_cast<const float4*>(main_in + gprim + cc * 8 + 4 * i);
            float4 b = *reinterpret_cast<const float4*>(main_in + gseco + cc * 8 + 4 * i);
            qp[4 * i + 0] = a.x; qp[4 * i + 1] = a.y; qp[4 * i + 2] = a.z; qp[4 * i + 3] = a.w;
            qs[4 * i + 0] = b.x; qs[4 * i + 1] = b.y; qs[4 * i + 2] = b.z; qs[4 * i + 3] = b.w;
        }
        #pragma unroll
        for (int c = 0; c < 8; c++) {
            const float* base = smem + (cc * 8 + c) * CHST + sbase;
            #pragma unroll
            for (int r = 0; r < 4; r++) {
                #pragma unroll
                for (int dw = 0; dw < K; dw++) {
                    float v = base[r * HWS + dw];
                    prim[r * 7 + dw] = fmaf(v, qp[c], prim[r * 7 + dw]);
                    seco[r * 7 + dw] = fmaf(v, qs[c], seco[r * 7 + dw]);
                }
            }
        }
    }

    // ---- Split softmax: combine pair lanes via shfl_xor(16) ----
    // (OOB halo positions carry score 0 and are included, matching reference.)
    float lmP = -1e30f, lmS = -1e30f;
    #pragma unroll
    for (int i = 0; i < 28; i++) lmP = fmaxf(lmP, prim[i]);
    #pragma unroll
    for (int r = 0; r < 4; r++) {
        bool valid = half ? (r <= 2) : (r >= 1);
        #pragma unroll
        for (int dw = 0; dw < K; dw++) {
            float s = valid ? seco[r * 7 + dw] : -1e30f;
            lmS = fmaxf(lmS, s);
        }
    }
    float gmP = fmaxf(lmP, __shfl_xor_sync(0xffffffffu, lmS, 16));
    float gmS = fmaxf(lmS, __shfl_xor_sync(0xffffffffu, lmP, 16));

    float lsP = 0.f, lsS = 0.f;
    #pragma unroll
    for (int i = 0; i < 28; i++) {
        prim[i] = __expf(prim[i] - gmP);
        lsP += prim[i];
    }
    #pragma unroll
    for (int r = 0; r < 4; r++) {
        bool valid = half ? (r <= 2) : (r >= 1);
        #pragma unroll
        for (int dw = 0; dw < K; dw++) {
            float e = valid ? __expf(seco[r * 7 + dw] - gmS) : 0.f;
            seco[r * 7 + dw] = e;
            lsS += e;
        }
    }
    float gsP = lsP + __shfl_xor_sync(0xffffffffu, lsS, 16);
    float gsS = lsS + __shfl_xor_sync(0xffffffffu, lsP, 16);
    float ivP = 1.f / gsP, ivS = 1.f / gsS;
    #pragma unroll
    for (int i = 0; i < 28; i++) { prim[i] *= ivP; seco[i] *= ivS; }
    // garbage seco rows now hold weight 0 -> pass 2 is branch-free.

    // ---- Stage val halo (reuse buffer) ----
    __syncthreads();
    stage_halo(smem, val_in, bx, by, tid);
    __syncthreads();

    // ---- Pass 2: partial outputs; combine with partner lane; store ----
    #pragma unroll
    for (int g = 0; g < 8; g++) {
        float oP[4] = {0.f, 0.f, 0.f, 0.f};
        float oS[4] = {0.f, 0.f, 0.f, 0.f};
        #pragma unroll
        for (int c = 0; c < 4; c++) {
            const float* base = smem + ((g << 2) + c) * CHST + sbase;
            #pragma unroll
            for (int r = 0; r < 4; r++) {
                #pragma unroll
                for (int dw = 0; dw < K; dw++) {
                    float v = base[r * HWS + dw];
                    oP[c] = fmaf(v, prim[r * 7 + dw], oP[c]);
                    oS[c] = fmaf(v, seco[r * 7 + dw], oS[c]);
                }
            }
        }
        // partner's oS is the other half of my primary pixel
        float f0 = oP[0] + __shfl_xor_sync(0xffffffffu, oS[0], 16);
        float f1 = oP[1] + __shfl_xor_sync(0xffffffffu, oS[1], 16);
        float f2 = oP[2] + __shfl_xor_sync(0xffffffffu, oS[2], 16);
        float f3 = oP[3] + __shfl_xor_sync(0xffffffffu, oS[3], 16);
        *reinterpret_cast<float4*>(out + gprim + (g << 2)) =
            make_float4(f0, f1, f2, f3);
    }
}

extern "C" void kernel_launch(void* const* d_in, const int* in_sizes, int n_in,
                              void* d_out, int out_size) {
    const float* main_in = (const float*)d_in[0];
    const float* ref_in  = (const float*)d_in[1];
    const float* val_in  = (const float*)d_in[2];
    float* out = (float*)d_out;

    cudaFuncSetAttribute(local_attn_kernel,
                         cudaFuncAttributeMaxDynamicSharedMemorySize, SMEM_BYTES);

    dim3 grid(W_IMG / TX, H_IMG / TY);
    local_attn_kernel<<<grid, NTHREADS, SMEM_BYTES>>>(main_in, ref_in, val_in, out);
}

// round 12
// speedup vs baseline: 1.2031x; 1.1050x over previous
#include <cuda_runtime.h>

// Windowed local attention, k=7, H=W=256, C=32, fp32.
// Thread = (2x2 pixel QUAD, union-row quarter). Quad union window 8x8:
// 16 loads/channel serve ~49 MACs -> compute crossbar bytes 267MB (vs 467).
// Softmax stats via 16 shfl; pass-2 partial outputs combined through a
// per-warp smem scratch (conflict-free stride-68 layout), NOT shfl.
// Tile 32x8 px = 64 quads, 256 threads, halo 38x14 (row stride 40).

#define H_IMG 256
#define W_IMG 256
#define C 32
#define K 7
#define PAD 3
#define TX 32
#define TY 8
#define HW 38               // used halo cols
#define HWS 40              // padded row stride (2*40 % 32 == 16)
#define HH 14               // TY + 6
#define CHST (HH * HWS)     // 560 floats per channel
#define NTHREADS 256
#define CMB_OFF (C * CHST)  // 17920 floats: combine scratch after halo
#define CMB_WARP 544        // 8 quads * 68 floats
#define SMEM_BYTES ((CMB_OFF + 8 * CMB_WARP) * 4)   // 89088

// Stage one tensor's halo: [c][row*HWS + col], zero-padded OOB.
__device__ __forceinline__ void stage_halo(float* __restrict__ buf,
                                           const float* __restrict__ src,
                                           int bx, int by, int tid) {
    for (int p = tid; p < HW * HH; p += NTHREADS) {
        int hp = p / HW;
        int wp = p - hp * HW;
        int gw = bx * TX - PAD + wp;
        int gh = by * TY - PAD + hp;
        bool ok = (gw >= 0) && (gw < W_IMG) && (gh >= 0) && (gh < H_IMG);
        int sa = hp * HWS + wp;
        int ga = ((gh << 8) + gw) * C;
        #pragma unroll
        for (int g = 0; g < 8; g++) {
            float4 r = make_float4(0.f, 0.f, 0.f, 0.f);
            if (ok) r = *reinterpret_cast<const float4*>(src + ga + (g << 2));
            float* d = buf + (g << 2) * CHST + sa;
            d[0 * CHST] = r.x;
            d[1 * CHST] = r.y;
            d[2 * CHST] = r.z;
            d[3 * CHST] = r.w;
        }
    }
}

__global__ __launch_bounds__(NTHREADS, 2)
void local_attn_kernel(const float* __restrict__ main_in,
                       const float* __restrict__ ref_in,
                       const float* __restrict__ val_in,
                       float* __restrict__ out) {
    extern __shared__ float smem[];
    float* halo = smem;
    float* cmb  = smem + CMB_OFF;

    const int tid  = threadIdx.x;
    const int bx   = blockIdx.x, by = blockIdx.y;
    const int w    = tid >> 5;
    const int lane = tid & 31;
    const int q    = lane >> 3;               // union-row quarter 0..3
    const int qx   = lane & 7;
    const int qy   = w >> 1;                  // quad row 0..3
    const int qc   = ((w & 1) << 3) + qx;     // quad col 0..15

    // This thread's 2 union rows start at halo row 2qy+2q; cols 2qc..2qc+7.
    const int sbase = (2 * qy + 2 * q) * HWS + 2 * qc;

    // Global pixel offsets for the quad's 4 pixels (p = py*2+px_).
    int gp[4];
    #pragma unroll
    for (int p = 0; p < 4; p++) {
        int gy = by * TY + 2 * qy + (p >> 1);
        int gx = bx * TX + 2 * qc + (p & 1);
        gp[p] = ((gy << 8) + gx) * C;
    }

    // Row-validity masks (runtime q, compile-time py/lr):
    // invalid iff (q==0 && py==1 && lr==0) || (q==3 && py==0 && lr==1)
    const bool inv0 = (q == 0);
    const bool inv3 = (q == 3);

    // ---- Stage ref halo ----
    stage_halo(halo, ref_in, bx, by, tid);
    __syncthreads();

    // ---- Pass 1: partial scores sc[py][px_][lr][dw] ----
    float sc[56];
    #pragma unroll
    for (int i = 0; i < 56; i++) sc[i] = 0.f;

    #pragma unroll
    for (int cc = 0; cc < 4; cc++) {          // 8-channel chunks
        float qr[4][8];
        #pragma unroll
        for (int p = 0; p < 4; p++) {
            float4 a = *reinterpret_cast<const float4*>(main_in + gp[p] + cc * 8);
            float4 b = *reinterpret_cast<const float4*>(main_in + gp[p] + cc * 8 + 4);
            qr[p][0] = a.x; qr[p][1] = a.y; qr[p][2] = a.z; qr[p][3] = a.w;
            qr[p][4] = b.x; qr[p][5] = b.y; qr[p][6] = b.z; qr[p][7] = b.w;
        }
        #pragma unroll
        for (int c = 0; c < 8; c++) {
            const float* bp = halo + (cc * 8 + c) * CHST + sbase;
            float vv[16];                      // [lr][u]
            #pragma unroll
            for (int lr = 0; lr < 2; lr++) {
                #pragma unroll
                for (int j = 0; j < 4; j++) {
                    float2 t = *reinterpret_cast<const float2*>(bp + lr * HWS + 2 * j);
                    vv[lr * 8 + 2 * j]     = t.x;
                    vv[lr * 8 + 2 * j + 1] = t.y;
                }
            }
            #pragma unroll
            for (int py = 0; py < 2; py++)
            #pragma unroll
            for (int px_ = 0; px_ < 2; px_++)
            #pragma unroll
            for (int lr = 0; lr < 2; lr++)
            #pragma unroll
            for (int dw = 0; dw < K; dw++) {
                int idx = ((py * 2 + px_) * 2 + lr) * 7 + dw;
                sc[idx] = fmaf(vv[lr * 8 + dw + px_], qr[py * 2 + px_][c], sc[idx]);
            }
        }
    }

    // ---- Distributed softmax (OOB halo positions score 0, included) ----
    float mx[4], sm[4];
    #pragma unroll
    for (int p = 0; p < 4; p++) {
        int py = p >> 1;
        float m = -1e30f;
        #pragma unroll
        for (int lr = 0; lr < 2; lr++) {
            bool bad = (py == 1 && lr == 0) ? inv0 : ((py == 0 && lr == 1) ? inv3 : false);
            #pragma unroll
            for (int dw = 0; dw < K; dw++) {
                float v = bad ? -1e30f : sc[(p * 2 + lr) * 7 + dw];
                m = fmaxf(m, v);
            }
        }
        mx[p] = m;
    }
    #pragma unroll
    for (int p = 0; p < 4; p++) {
        mx[p] = fmaxf(mx[p], __shfl_xor_sync(0xffffffffu, mx[p], 8));
        mx[p] = fmaxf(mx[p], __shfl_xor_sync(0xffffffffu, mx[p], 16));
    }
    #pragma unroll
    for (int p = 0; p < 4; p++) {
        int py = p >> 1;
        float s = 0.f;
        #pragma unroll
        for (int lr = 0; lr < 2; lr++) {
            bool bad = (py == 1 && lr == 0) ? inv0 : ((py == 0 && lr == 1) ? inv3 : false);
            #pragma unroll
            for (int dw = 0; dw < K; dw++) {
                int idx = (p * 2 + lr) * 7 + dw;
                float e = bad ? 0.f : __expf(sc[idx] - mx[p]);
                sc[idx] = e;
                s += e;
            }
        }
        sm[p] = s;
    }
    #pragma unroll
    for (int p = 0; p < 4; p++) {
        sm[p] += __shfl_xor_sync(0xffffffffu, sm[p], 8);
        sm[p] += __shfl_xor_sync(0xffffffffu, sm[p], 16);
        float iv = 1.f / sm[p];
        #pragma unroll
        for (int i = 0; i < 14; i++) sc[p * 14 + i] *= iv;
    }

    // ---- Stage val halo (reuse buffer) ----
    __syncthreads();
    stage_halo(halo, val_in, bx, by, tid);
    __syncthreads();

    // ---- Pass 2: partial outputs per 4-channel group; smem combine ----
    float* cw = cmb + w * CMB_WARP + qx * 68;
    #pragma unroll
    for (int g = 0; g < 8; g++) {
        float acc[16];                         // [p][c]
        #pragma unroll
        for (int i = 0; i < 16; i++) acc[i] = 0.f;

        #pragma unroll
        for (int c = 0; c < 4; c++) {
            const float* bp = halo + (g * 4 + c) * CHST + sbase;
            float vv[16];
            #pragma unroll
            for (int lr = 0; lr < 2; lr++) {
                #pragma unroll
                for (int j = 0; j < 4; j++) {
                    float2 t = *reinterpret_cast<const float2*>(bp + lr * HWS + 2 * j);
                    vv[lr * 8 + 2 * j]     = t.x;
                    vv[lr * 8 + 2 * j + 1] = t.y;
                }
            }
            #pragma unroll
            for (int py = 0; py < 2; py++)
            #pragma unroll
            for (int px_ = 0; px_ < 2; px_++)
            #pragma unroll
            for (int lr = 0; lr < 2; lr++)
            #pragma unroll
            for (int dw = 0; dw < K; dw++) {
                int p = py * 2 + px_;
                acc[p * 4 + c] = fmaf(vv[lr * 8 + dw + px_],
                                      sc[(p * 2 + lr) * 7 + dw], acc[p * 4 + c]);
            }
        }

        // write partials for the 3 non-owned pixels (conflict-free layout)
        #pragma unroll
        for (int j = 1; j < 4; j++) {
            int p = (q + j) & 3;
            *reinterpret_cast<float4*>(cw + p * 16 + q * 4) =
                make_float4(acc[p * 4 + 0], acc[p * 4 + 1],
                            acc[p * 4 + 2], acc[p * 4 + 3]);
        }
        __syncwarp();
        float o0 = acc[q * 4 + 0], o1 = acc[q * 4 + 1];
        float o2 = acc[q * 4 + 2], o3 = acc[q * 4 + 3];
        #pragma unroll
        for (int j = 1; j < 4; j++) {
            int o = (q + j) & 3;
            float4 t = *reinterpret_cast<const float4*>(cw + q * 16 + o * 4);
            o0 += t.x; o1 += t.y; o2 += t.z; o3 += t.w;
        }
        __syncwarp();                          // reads done before next group's writes

        *reinterpret_cast<float4*>(out + gp[q] + g * 4) =
            make_float4(o0, o1, o2, o3);
    }
}

extern "C" void kernel_launch(void* const* d_in, const int* in_sizes, int n_in,
                              void* d_out, int out_size) {
    const float* main_in = (const float*)d_in[0];
    const float* ref_in  = (const float*)d_in[1];
    const float* val_in  = (const float*)d_in[2];
    float* out = (float*)d_out;

    cudaFuncSetAttribute(local_attn_kernel,
                         cudaFuncAttributeMaxDynamicSharedMemorySize, SMEM_BYTES);

    dim3 grid(W_IMG / TX, H_IMG / TY);
    local_attn_kernel<<<grid, NTHREADS, SMEM_BYTES>>>(main_in, ref_in, val_in, out);
}